// round 8
// baseline (speedup 1.0000x reference)
#include <cuda_runtime.h>
#include <cuda_bf16.h>
#include <cstdint>

#define NNODES 16383
#define EMBED 512
#define NLEV 16
#define LEAVES 8192
#define MAXM 4096

// ---------------- device scratch (static, no runtime alloc) ----------------
__device__ __nv_bfloat16 g_Hhi[(size_t)NNODES * EMBED];    // 16.8 MB
__device__ __nv_bfloat16 g_Hlo[(size_t)NNODES * EMBED];    // 16.8 MB
__device__ __nv_bfloat16 g_Whi[(size_t)EMBED * 2 * EMBED]; // 1 MB
__device__ __nv_bfloat16 g_Wlo[(size_t)EMBED * 2 * EMBED]; // 1 MB
__device__ int g_list[NLEV][MAXM];
__device__ int g_cnt[NLEV];

// ================= helpers =================
__device__ __forceinline__ uint32_t smem_u32(const void* p) {
    uint32_t a;
    asm("{ .reg .u64 t; cvta.to.shared.u64 t, %1; cvt.u32.u64 %0, t; }" : "=r"(a) : "l"(p));
    return a;
}
__device__ __forceinline__ void cp16(uint32_t s, const void* g) {
    asm volatile("cp.async.cg.shared.global [%0], [%1], 16;" :: "r"(s), "l"(g));
}
__device__ __forceinline__ void ldm4(uint32_t* r, uint32_t addr) {
    asm volatile("ldmatrix.sync.aligned.m8n8.x4.shared.b16 {%0,%1,%2,%3}, [%4];"
        : "=r"(r[0]), "=r"(r[1]), "=r"(r[2]), "=r"(r[3]) : "r"(addr));
}
__device__ __forceinline__ void mma16816(float* c, const uint32_t* a,
                                         uint32_t b0, uint32_t b1) {
    asm volatile(
        "mma.sync.aligned.m16n8k16.row.col.f32.bf16.bf16.f32 "
        "{%0,%1,%2,%3}, {%4,%5,%6,%7}, {%8,%9}, {%0,%1,%2,%3};"
        : "+f"(c[0]), "+f"(c[1]), "+f"(c[2]), "+f"(c[3])
        : "r"(a[0]), "r"(a[1]), "r"(a[2]), "r"(a[3]), "r"(b0), "r"(b1));
}

// ================= schedule =================
__global__ void k_zero() { if (threadIdx.x < NLEV) g_cnt[threadIdx.x] = 0; }

__global__ void k_bucket(const int* __restrict__ is_leaf, const int* __restrict__ left) {
    int i = blockIdx.x * blockDim.x + threadIdx.x;
    if (i >= NNODES || is_leaf[i]) return;
    int c = left[i], d = 1;
    while (!is_leaf[c]) { c = left[c]; d++; if (d >= NLEV) break; }
    if (d >= NLEV) d = NLEV - 1;
    int slot = atomicAdd(&g_cnt[d], 1);
    if (slot < MAXM) g_list[d][slot] = i;
}

// ================= leaves -> hi/lo bf16 =================
__global__ void k_leaf(const int* __restrict__ is_leaf, const int* __restrict__ word,
                       const float4* __restrict__ emb4) {
    int t = blockIdx.x * blockDim.x + threadIdx.x;
    int node = t >> 7;
    if (node >= NNODES) return;
    if (!is_leaf[node]) return;
    int j = t & 127;
    float4 v = emb4[(size_t)word[node] * 128 + j];
    float a[4] = {fmaxf(v.x, 0.f), fmaxf(v.y, 0.f), fmaxf(v.z, 0.f), fmaxf(v.w, 0.f)};
    size_t base = (size_t)node * EMBED + j * 4;
#pragma unroll
    for (int p = 0; p < 2; p++) {
        __nv_bfloat16 h0 = __float2bfloat16(a[2 * p]);
        __nv_bfloat16 h1 = __float2bfloat16(a[2 * p + 1]);
        __nv_bfloat162 hp; hp.x = h0; hp.y = h1;
        __nv_bfloat162 lp;
        lp.x = __float2bfloat16(a[2 * p] - __bfloat162float(h0));
        lp.y = __float2bfloat16(a[2 * p + 1] - __bfloat162float(h1));
        *reinterpret_cast<__nv_bfloat162*>(&g_Hhi[base + 2 * p]) = hp;
        *reinterpret_cast<__nv_bfloat162*>(&g_Hlo[base + 2 * p]) = lp;
    }
}

// ================= W -> hi/lo prep =================
__global__ void k_wprep(const float* __restrict__ W) {
    int i = blockIdx.x * blockDim.x + threadIdx.x;
    if (i >= EMBED * 1024) return;
    float v = W[i];
    __nv_bfloat16 h = __float2bfloat16(v);
    g_Whi[i] = h;
    g_Wlo[i] = __float2bfloat16(v - __bfloat162float(h));
}

// ================= HMMA level GEMM =================
// C[m,n] = sum_k pair[m,k] * W[n,k],  pair = [H[left]; H[right]] as bf16 hi/lo.
// BM=64, BN=64, BK=32, 128 threads (2x2 warps, warp tile 32x32).
// Smem tiles stride 40 bf16 (80 B) -> ldmatrix conflict-free.
#define BK 32
#define STR 40
#define TILE_ELEMS (64 * STR)

__global__ __launch_bounds__(128) void k_hmma(
    int d, const int* __restrict__ left, const int* __restrict__ right,
    const float* __restrict__ bW)
{
    __shared__ __align__(16) __nv_bfloat16 sm[2][4][TILE_ELEMS]; // {Ahi,Alo,Bhi,Blo}
    __shared__ int s_node[64], s_srcL[64], s_srcR[64];

    int cnt = g_cnt[d];
    if (cnt == 0) return;
    int tid = threadIdx.x;
    int lane = tid & 31, warp = tid >> 5;
    int wm = warp >> 1, wn = warp & 1;
    int mbase = blockIdx.x * 64;
    int n0 = blockIdx.y * 64;

    if (tid < 64) {
        int m = mbase + tid;
        int node = 0, sl = 0, sr = 0;
        if (m < cnt) { node = g_list[d][m]; sl = left[node]; sr = right[node]; }
        s_node[tid] = node; s_srcL[tid] = sl; s_srcR[tid] = sr;
    }
    __syncthreads();

    uint32_t smb[2][4];
#pragma unroll
    for (int b = 0; b < 2; b++)
#pragma unroll
        for (int t = 0; t < 4; t++) smb[b][t] = smem_u32(sm[b][t]);

    const char* HhiB = (const char*)g_Hhi;
    const char* HloB = (const char*)g_Hlo;
    const char* WhiB = (const char*)g_Whi;
    const char* WloB = (const char*)g_Wlo;

    // ---- async load of one BK chunk into buffer `buf` ----
    auto load_chunk = [&](int c, int buf) {
        int koffA = (c & 15) * BK;          // within child's 512 cols
        int koffW = c * BK;                 // within W's 1024 cols
        const int* srcA = (c < 16) ? s_srcL : s_srcR;
#pragma unroll
        for (int rep = 0; rep < 2; rep++) {
            int s = tid + rep * 128;        // 0..255
            int row = s >> 2, seg = s & 3;
            uint32_t soff = (uint32_t)(row * (STR * 2) + seg * 16);
            size_t ga = ((size_t)srcA[row] * EMBED + koffA) * 2 + seg * 16;
            cp16(smb[buf][0] + soff, HhiB + ga);
            cp16(smb[buf][1] + soff, HloB + ga);
            size_t gb = ((size_t)(n0 + row) * 1024 + (size_t)koffW) * 2 + seg * 16;
            cp16(smb[buf][2] + soff, WhiB + gb);
            cp16(smb[buf][3] + soff, WloB + gb);
        }
        asm volatile("cp.async.commit_group;" ::: "memory");
    };

    float acc[2][4][4];
#pragma unroll
    for (int i = 0; i < 2; i++)
#pragma unroll
        for (int j = 0; j < 4; j++)
#pragma unroll
            for (int q = 0; q < 4; q++) acc[i][j][q] = 0.f;

    load_chunk(0, 0);

#pragma unroll 1
    for (int c = 0; c < 32; c++) {
        int buf = c & 1;
        if (c + 1 < 32) {
            load_chunk(c + 1, buf ^ 1);
            asm volatile("cp.async.wait_group 1;" ::: "memory");
        } else {
            asm volatile("cp.async.wait_group 0;" ::: "memory");
        }
        __syncthreads();

#pragma unroll
        for (int kk = 0; kk < 2; kk++) {
            int coloff = kk * 16 + ((lane >> 4) << 3);
            uint32_t ah[2][4], al[2][4];
#pragma unroll
            for (int mi = 0; mi < 2; mi++) {
                int row = wm * 32 + mi * 16 + (lane & 15);
                uint32_t off = (uint32_t)(row * STR + coloff) * 2;
                ldm4(ah[mi], smb[buf][0] + off);
                ldm4(al[mi], smb[buf][1] + off);
            }
            uint32_t bh[2][4], bl[2][4];
#pragma unroll
            for (int j = 0; j < 2; j++) {
                int row = wn * 32 + j * 16 + (lane & 15);
                uint32_t off = (uint32_t)(row * STR + coloff) * 2;
                ldm4(bh[j], smb[buf][2] + off);
                ldm4(bl[j], smb[buf][3] + off);
            }
#pragma unroll
            for (int mi = 0; mi < 2; mi++)
#pragma unroll
                for (int nj = 0; nj < 4; nj++) {
                    int j = nj >> 1, sub = nj & 1;
                    float* cc = acc[mi][nj];
                    mma16816(cc, ah[mi], bh[j][sub], bh[j][sub + 2]);  // hi*hi
                    mma16816(cc, ah[mi], bl[j][sub], bl[j][sub + 2]);  // hi*lo
                    mma16816(cc, al[mi], bh[j][sub], bh[j][sub + 2]);  // lo*hi
                }
        }
        __syncthreads();
    }

    // ---- epilogue: bias + relu + hi/lo split-store ----
#pragma unroll
    for (int mi = 0; mi < 2; mi++)
#pragma unroll
        for (int nj = 0; nj < 4; nj++) {
            int lrow = wm * 32 + mi * 16 + (lane >> 2);
            int n = n0 + wn * 32 + nj * 8 + (lane & 3) * 2;
            float b0 = bW[n], b1 = bW[n + 1];
#pragma unroll
            for (int half = 0; half < 2; half++) {
                int lm = lrow + half * 8;
                int m = mbase + lm;
                if (m < cnt) {
                    int node = s_node[lm];
                    float v0 = fmaxf(acc[mi][nj][2 * half]     + b0, 0.f);
                    float v1 = fmaxf(acc[mi][nj][2 * half + 1] + b1, 0.f);
                    __nv_bfloat16 h0 = __float2bfloat16(v0);
                    __nv_bfloat16 h1 = __float2bfloat16(v1);
                    __nv_bfloat162 hp; hp.x = h0; hp.y = h1;
                    __nv_bfloat162 lp;
                    lp.x = __float2bfloat16(v0 - __bfloat162float(h0));
                    lp.y = __float2bfloat16(v1 - __bfloat162float(h1));
                    size_t base = (size_t)node * EMBED + n;
                    *reinterpret_cast<__nv_bfloat162*>(&g_Hhi[base]) = hp;
                    *reinterpret_cast<__nv_bfloat162*>(&g_Hlo[base]) = lp;
                }
            }
        }
}

// ================= small levels (<=32 nodes): warp-per-output FFMA =================
__global__ __launch_bounds__(256) void k_small(
    int d, const int* __restrict__ left, const int* __restrict__ right,
    const float* __restrict__ W, const float* __restrict__ bW) {
    int cnt = g_cnt[d];
    __shared__ float pairf[1024];
    int tid = threadIdx.x, lane = tid & 31, w = tid >> 5;
    int n0 = blockIdx.y << 7;
    for (int bx = blockIdx.x; bx < cnt; bx += gridDim.x) {
        int node = g_list[d][bx];
        int cl = left[node], cr = right[node];
        __syncthreads();
#pragma unroll
        for (int j = 0; j < 4; j++) {
            int i = tid + j * 256;
            int child = (i < 512) ? cl : cr;
            int col = i & 511;
            pairf[i] = __bfloat162float(g_Hhi[(size_t)child * EMBED + col]) +
                       __bfloat162float(g_Hlo[(size_t)child * EMBED + col]);
        }
        __syncthreads();
#pragma unroll 1
        for (int o = 0; o < 16; o++) {
            int n = n0 + w * 16 + o;
            const float* wr = W + (size_t)n * 1024;
            float acc = 0.f;
#pragma unroll
            for (int it = 0; it < 32; it++)
                acc += wr[it * 32 + lane] * pairf[it * 32 + lane];
#pragma unroll
            for (int off = 16; off; off >>= 1)
                acc += __shfl_xor_sync(0xffffffffu, acc, off);
            if (lane == 0) {
                float v = fmaxf(acc + bW[n], 0.f);
                __nv_bfloat16 h = __float2bfloat16(v);
                g_Hhi[(size_t)node * EMBED + n] = h;
                g_Hlo[(size_t)node * EMBED + n] = __float2bfloat16(v - __bfloat162float(h));
            }
        }
    }
}

// ================= logits =================
__global__ void k_logits(const float* __restrict__ P, const float* __restrict__ bP,
                         float* __restrict__ out) {
    int gw = (blockIdx.x * blockDim.x + threadIdx.x) >> 5;
    int lane = threadIdx.x & 31;
    if (gw >= NNODES) return;
    const uint32_t* Hh = (const uint32_t*)g_Hhi;
    const uint32_t* Hl = (const uint32_t*)g_Hlo;
    float h[16];
#pragma unroll
    for (int j = 0; j < 8; j++) {
        uint32_t uh = Hh[(size_t)gw * 256 + lane * 8 + j];
        uint32_t ul = Hl[(size_t)gw * 256 + lane * 8 + j];
        __nv_bfloat162 bh = *reinterpret_cast<__nv_bfloat162*>(&uh);
        __nv_bfloat162 bl = *reinterpret_cast<__nv_bfloat162*>(&ul);
        h[2 * j]     = __bfloat162float(bh.x) + __bfloat162float(bl.x);
        h[2 * j + 1] = __bfloat162float(bh.y) + __bfloat162float(bl.y);
    }
#pragma unroll
    for (int c = 0; c < 5; c++) {
        float acc = 0.f;
#pragma unroll
        for (int k = 0; k < 16; k++)
            acc += P[(size_t)c * EMBED + lane * 16 + k] * h[k];
#pragma unroll
        for (int off = 16; off; off >>= 1)
            acc += __shfl_xor_sync(0xffffffffu, acc, off);
        if (lane == 0) out[(size_t)gw * 5 + c] = acc + bP[c];
    }
}

// ================= launch =================
extern "C" void kernel_launch(void* const* d_in, const int* in_sizes, int n_in,
                              void* d_out, int out_size) {
    const int*   is_leaf = (const int*)d_in[0];
    const int*   word    = (const int*)d_in[1];
    const int*   left    = (const int*)d_in[2];
    const int*   right   = (const int*)d_in[3];
    const float* emb     = (const float*)d_in[4];
    const float* W       = (const float*)d_in[5];
    const float* bW      = (const float*)d_in[6];
    const float* P       = (const float*)d_in[7];
    const float* bP      = (const float*)d_in[8];
    float* out = (float*)d_out;

    k_zero<<<1, 32>>>();
    k_bucket<<<(NNODES + 255) / 256, 256>>>(is_leaf, left);
    k_leaf<<<(NNODES * 128 + 255) / 256, 256>>>(is_leaf, word, (const float4*)emb);
    k_wprep<<<(EMBED * 1024 + 255) / 256, 256>>>(W);

    for (int d = 1; d <= 7; d++) {            // cnt = 4096 .. 64 -> HMMA path
        int cnt = LEAVES >> d;
        k_hmma<<<dim3(cnt / 64, 8), 128>>>(d, left, right, bW);
    }
    for (int d = 8; d <= 13; d++) {           // cnt = 32 .. 1 -> FFMA path
        int cnt = LEAVES >> d;
        k_small<<<dim3(cnt, 4), 256>>>(d, left, right, W, bW);
    }

    k_logits<<<(NNODES * 32 + 255) / 256, 256>>>(P, bP, out);
}

// round 9
// speedup vs baseline: 1.1376x; 1.1376x over previous
#include <cuda_runtime.h>
#include <cstdint>

#define NNODES 16383
#define EMBED 512
#define E4 128          // float4 per H row
#define NLEV 16
#define LEAVES 8192
#define MAXM 4096

// ---------------- device scratch (static, no runtime alloc) ----------------
__device__ float4 g_H[NNODES * E4];          // 33.5 MB hidden states
__device__ float4 g_part[8 * MAXM * E4];     // 67 MB split-K partials
__device__ int    g_list[NLEV][MAXM];
__device__ int    g_cnt[NLEV];

// ---------------- f32x2 helpers ----------------
__device__ __forceinline__ void fma2(unsigned long long& d,
                                     unsigned long long a, unsigned long long b) {
    asm("fma.rn.f32x2 %0, %1, %2, %0;" : "+l"(d) : "l"(a), "l"(b));
}
__device__ __forceinline__ unsigned long long pk2(float x, float y) {
    unsigned long long r;
    asm("mov.b64 %0, {%1, %2};" : "=l"(r) : "f"(x), "f"(y));
    return r;
}
__device__ __forceinline__ float2 upk2(unsigned long long v) {
    float2 r;
    asm("mov.b64 {%0, %1}, %2;" : "=f"(r.x), "=f"(r.y) : "l"(v));
    return r;
}

// ---------------- schedule kernels ----------------
__global__ void k_zero() {
    if (threadIdx.x < NLEV) g_cnt[threadIdx.x] = 0;
}

__global__ void k_bucket(const int* __restrict__ is_leaf,
                         const int* __restrict__ left) {
    int i = blockIdx.x * blockDim.x + threadIdx.x;
    if (i >= NNODES) return;
    if (is_leaf[i]) return;
    int c = left[i];
    int d = 1;
    while (!is_leaf[c]) { c = left[c]; d++; if (d >= NLEV) break; }
    if (d >= NLEV) d = NLEV - 1;
    int slot = atomicAdd(&g_cnt[d], 1);
    if (slot < MAXM) g_list[d][slot] = i;
}

// ---------------- leaves: H[i] = relu(emb[word[i]]) ----------------
__global__ void k_leaf(const int* __restrict__ is_leaf,
                       const int* __restrict__ word,
                       const float4* __restrict__ emb4) {
    int t = blockIdx.x * blockDim.x + threadIdx.x;
    int node = t >> 7;
    if (node >= NNODES) return;
    if (!is_leaf[node]) return;
    int j = t & 127;
    float4 v = emb4[word[node] * E4 + j];
    v.x = fmaxf(v.x, 0.f); v.y = fmaxf(v.y, 0.f);
    v.z = fmaxf(v.z, 0.f); v.w = fmaxf(v.w, 0.f);
    g_H[node * E4 + j] = v;
}

// ---------------- split-K GEMM partial (f32x2 inner, reg double-buffer) ----
// out_part[z][m][n] = sum over K-chunk z of W[n][k] * pair[m][k]
// BM=128, BN=128, BK=16, 256 threads, 8x8 micro-tile (acc as 8x4 f32x2 pairs).
__global__ __launch_bounds__(256, 2) void k_partial(
    int d, int ZS,
    const int* __restrict__ left, const int* __restrict__ right,
    const float4* __restrict__ W4)
{
    int cnt = g_cnt[d];
    if (cnt == 0) return;
    const int* list = g_list[d];

    int z  = blockIdx.z;
    int n0 = blockIdx.y << 7;           // output-col tile base (0..384)
    int kchunk4 = 256 / ZS;             // float4s per K chunk (64 or 32)
    int aoff4 = (z & ((ZS >> 1) - 1)) * kchunk4;   // within-child col (f4)
    int woff4 = z * kchunk4;                        // within-W col (f4)
    bool useRight = (z >= (ZS >> 1));

    __shared__ float As[16 * 132];
    __shared__ float Bs[16 * 132];
    __shared__ int s_src[128];

    int tid = threadIdx.x;
    int tx = tid & 15, ty = tid >> 4;   // thread tile: n = tx*8, m = ty*8
    int c4  = tid & 3;                  // k-f4 chunk within BK tile
    int row = tid >> 2;                 // 0..63 (row index for loading)
    int mtiles = (cnt + 127) >> 7;

    for (int bm = blockIdx.x; bm < mtiles; bm += gridDim.x) {
        if (tid < 128) {
            int m = bm * 128 + tid;
            int src = 0;
            if (m < cnt) {
                int node = list[m];
                src = useRight ? right[node] : left[node];
            }
            s_src[tid] = src;
        }
        __syncthreads();

        unsigned long long acc[8][4];
#pragma unroll
        for (int i = 0; i < 8; i++)
#pragma unroll
            for (int j = 0; j < 4; j++) acc[i][j] = 0ull;

        // prefetch chunk 0 into registers
        float4 va[2], vb[2];
#pragma unroll
        for (int r = 0; r < 2; r++) {
            int mr = row + r * 64;
            va[r] = g_H[s_src[mr] * E4 + aoff4 + c4];
            vb[r] = W4[(n0 + mr) * 256 + woff4 + c4];
        }

        for (int k4 = 0; k4 < kchunk4; k4 += 4) {   // BK = 16 floats
            // store staged chunk to smem (transposed [k][m] / [k][n])
#pragma unroll
            for (int r = 0; r < 2; r++) {
                int mr = row + r * 64;
                As[(c4 * 4 + 0) * 132 + mr] = va[r].x;
                As[(c4 * 4 + 1) * 132 + mr] = va[r].y;
                As[(c4 * 4 + 2) * 132 + mr] = va[r].z;
                As[(c4 * 4 + 3) * 132 + mr] = va[r].w;
                Bs[(c4 * 4 + 0) * 132 + mr] = vb[r].x;
                Bs[(c4 * 4 + 1) * 132 + mr] = vb[r].y;
                Bs[(c4 * 4 + 2) * 132 + mr] = vb[r].z;
                Bs[(c4 * 4 + 3) * 132 + mr] = vb[r].w;
            }
            __syncthreads();

            // prefetch next chunk while computing this one
            if (k4 + 4 < kchunk4) {
#pragma unroll
                for (int r = 0; r < 2; r++) {
                    int mr = row + r * 64;
                    va[r] = g_H[s_src[mr] * E4 + aoff4 + k4 + 4 + c4];
                    vb[r] = W4[(n0 + mr) * 256 + woff4 + k4 + 4 + c4];
                }
            }

#pragma unroll
            for (int kk = 0; kk < 16; kk++) {
                float4 a0 = *(const float4*)&As[kk * 132 + ty * 8];
                float4 a1 = *(const float4*)&As[kk * 132 + ty * 8 + 4];
                float4 b0 = *(const float4*)&Bs[kk * 132 + tx * 8];
                float4 b1 = *(const float4*)&Bs[kk * 132 + tx * 8 + 4];
                unsigned long long bp[4];
                bp[0] = pk2(b0.x, b0.y);
                bp[1] = pk2(b0.z, b0.w);
                bp[2] = pk2(b1.x, b1.y);
                bp[3] = pk2(b1.z, b1.w);
                float a[8] = {a0.x, a0.y, a0.z, a0.w, a1.x, a1.y, a1.z, a1.w};
#pragma unroll
                for (int i = 0; i < 8; i++) {
                    unsigned long long ap = pk2(a[i], a[i]);
                    fma2(acc[i][0], ap, bp[0]);
                    fma2(acc[i][1], ap, bp[1]);
                    fma2(acc[i][2], ap, bp[2]);
                    fma2(acc[i][3], ap, bp[3]);
                }
            }
            __syncthreads();
        }

        float4* pout = g_part + (size_t)z * MAXM * E4;
#pragma unroll
        for (int i = 0; i < 8; i++) {
            int m = bm * 128 + ty * 8 + i;
            if (m < cnt) {
                float2 p0 = upk2(acc[i][0]);
                float2 p1 = upk2(acc[i][1]);
                float2 p2 = upk2(acc[i][2]);
                float2 p3 = upk2(acc[i][3]);
                pout[m * E4 + (n0 >> 2) + tx * 2 + 0] = make_float4(p0.x, p0.y, p1.x, p1.y);
                pout[m * E4 + (n0 >> 2) + tx * 2 + 1] = make_float4(p2.x, p2.y, p3.x, p3.y);
            }
        }
        __syncthreads();
    }
}

// ---------------- combine partials + bias + relu -> H ----------------
__global__ void k_combine(int d, int ZS, const float4* __restrict__ bW4) {
    int cnt = g_cnt[d];
    const int* list = g_list[d];
    int total = cnt * E4;
    for (int idx = blockIdx.x * blockDim.x + threadIdx.x; idx < total;
         idx += gridDim.x * blockDim.x) {
        int m = idx >> 7, j = idx & 127;
        float4 s = g_part[m * E4 + j];
        for (int z = 1; z < ZS; z++) {
            float4 p = g_part[((size_t)z * MAXM + m) * E4 + j];
            s.x += p.x; s.y += p.y; s.z += p.z; s.w += p.w;
        }
        float4 b = bW4[j];
        s.x = fmaxf(s.x + b.x, 0.f);
        s.y = fmaxf(s.y + b.y, 0.f);
        s.z = fmaxf(s.z + b.z, 0.f);
        s.w = fmaxf(s.w + b.w, 0.f);
        g_H[list[m] * E4 + j] = s;
    }
}

// ---------------- small levels (<=32 nodes): warp-per-output ----------------
__global__ __launch_bounds__(256) void k_small(
    int d, const int* __restrict__ left, const int* __restrict__ right,
    const float4* __restrict__ W4, const float* __restrict__ bW)
{
    int cnt = g_cnt[d];
    __shared__ float4 pair[256];   // 1024 floats = [h_l ; h_r]
    int tid = threadIdx.x;
    int lane = tid & 31, w = tid >> 5;
    int n0 = blockIdx.y << 7;      // 128 outputs per block
    float* Hf = (float*)g_H;

    for (int bx = blockIdx.x; bx < cnt; bx += gridDim.x) {
        int node = g_list[d][bx];
        int cl = left[node], cr = right[node];
        __syncthreads();
        pair[tid] = (tid < 128) ? g_H[cl * E4 + tid] : g_H[cr * E4 + tid - 128];
        __syncthreads();
#pragma unroll 1
        for (int o = 0; o < 16; o++) {
            int n = n0 + w * 16 + o;
            const float4* wrow = W4 + n * 256;
            float acc = 0.f;
#pragma unroll
            for (int it = 0; it < 8; it++) {
                float4 wv = wrow[lane + it * 32];
                float4 pv = pair[lane + it * 32];
                acc += wv.x * pv.x + wv.y * pv.y + wv.z * pv.z + wv.w * pv.w;
            }
#pragma unroll
            for (int off = 16; off; off >>= 1)
                acc += __shfl_xor_sync(0xffffffffu, acc, off);
            if (lane == 0)
                Hf[node * EMBED + n] = fmaxf(acc + bW[n], 0.f);
        }
    }
}

// ---------------- logits: out[i][c] = H[i] . P[c] + bP[c] ----------------
__global__ void k_logits(const float4* __restrict__ P4,
                         const float* __restrict__ bP,
                         float* __restrict__ out) {
    int gw = (blockIdx.x * blockDim.x + threadIdx.x) >> 5;
    int lane = threadIdx.x & 31;
    if (gw >= NNODES) return;
    float4 h[4];
#pragma unroll
    for (int i = 0; i < 4; i++) h[i] = g_H[gw * E4 + lane + i * 32];
#pragma unroll
    for (int c = 0; c < 5; c++) {
        float acc = 0.f;
#pragma unroll
        for (int i = 0; i < 4; i++) {
            float4 p = P4[c * E4 + lane + i * 32];
            acc += p.x * h[i].x + p.y * h[i].y + p.z * h[i].z + p.w * h[i].w;
        }
#pragma unroll
        for (int off = 16; off; off >>= 1)
            acc += __shfl_xor_sync(0xffffffffu, acc, off);
        if (lane == 0) out[gw * 5 + c] = acc + bP[c];
    }
}

// ---------------- launch ----------------
extern "C" void kernel_launch(void* const* d_in, const int* in_sizes, int n_in,
                              void* d_out, int out_size) {
    const int*   is_leaf = (const int*)d_in[0];
    const int*   word    = (const int*)d_in[1];
    const int*   left    = (const int*)d_in[2];
    const int*   right   = (const int*)d_in[3];
    const float* emb     = (const float*)d_in[4];
    const float* W       = (const float*)d_in[5];
    const float* bW      = (const float*)d_in[6];
    const float* P       = (const float*)d_in[7];
    const float* bP      = (const float*)d_in[8];
    float* out = (float*)d_out;

    k_zero<<<1, 32>>>();
    k_bucket<<<(NNODES + 255) / 256, 256>>>(is_leaf, left);
    k_leaf<<<(NNODES * 128 + 255) / 256, 256>>>(is_leaf, word, (const float4*)emb);

    for (int d = 1; d <= 13; d++) {
        int cnt = LEAVES >> d;   // expected level size (kernels read actual count)
        if (cnt >= 64) {
            int ZS = (d <= 3) ? 4 : 8;
            int mt = (cnt + 127) / 128; if (mt < 1) mt = 1;
            k_partial<<<dim3(mt, 4, ZS), 256>>>(d, ZS, left, right, (const float4*)W);
            int cb = (cnt * 128 + 255) / 256; if (cb < 1) cb = 1;
            k_combine<<<cb, 256>>>(d, ZS, (const float4*)bW);
        } else {
            int gx = cnt < 1 ? 1 : cnt;
            k_small<<<dim3(gx, 4), 256>>>(d, left, right, (const float4*)W, bW);
        }
    }

    k_logits<<<(NNODES * 32 + 255) / 256, 256>>>((const float4*)P, bP, out);
}